// round 17
// baseline (speedup 1.0000x reference)
#include <cuda_runtime.h>
#include <cuda_fp16.h>
#include <math.h>
#include <cstdint>

#define CDIM 128
#define BDIM 8
#define NDIM 2048

// --- GEMM: CTA m64 x n128, 512 thr (16 warps, m16 x n32), BK=64, 3 stages ---
#define NSTAGE 3
#define BK 64
#define NITER (NDIM / BK)          // 32
#define A_ROWP 72                  // halves per row (64 data + 8 pad) -> 144B stride
#define A_STB (64 * A_ROWP * 2)    // 9216 B per A stage
#define B_STB (129 * A_ROWP * 2)   // 18576 B per B stage (128 g rows + 1 w row)
#define B_OFFB (NSTAGE * A_STB)    // 27648
#define DEN_OFFB (B_OFFB + NSTAGE * B_STB)   // 83376
#define SMEM_TOTAL (DEN_OFFB + 4 * 64 * 4)   // 84400 B -> 2 CTAs/SM
#define NTHR 512

// ---------------- device scratch ----------------
__device__ __half g_gT[BDIM * CDIM * NDIM];  // [b][c][j] = fp16(w*h)
__device__ __half g_w[BDIM * NDIM];          // [b][j]    = fp16(w)

// ---------------- helpers ----------------
__device__ __forceinline__ uint32_t smem_u32(const void* p) {
    uint32_t a;
    asm("{ .reg .u64 t; cvta.to.shared.u64 t, %1; cvt.u32.u64 %0, t; }" : "=r"(a) : "l"(p));
    return a;
}
__device__ __forceinline__ void cp16(uint32_t dst, const void* src) {
    asm volatile("cp.async.cg.shared.global [%0], [%1], 16;" :: "r"(dst), "l"(src));
}
#define CP_COMMIT() asm volatile("cp.async.commit_group;" ::: "memory")
#define CP_WAIT1()  asm volatile("cp.async.wait_group 1;" ::: "memory")

#define LDSM_X4(r0, r1, r2, r3, a) \
    asm volatile("ldmatrix.sync.aligned.m8n8.x4.shared.b16 {%0,%1,%2,%3}, [%4];" \
        : "=r"(r0), "=r"(r1), "=r"(r2), "=r"(r3) : "r"(a))

#define MMA_F16(d, a0, a1, a2, a3, b0, b1) \
    asm volatile("mma.sync.aligned.m16n8k16.row.col.f32.f16.f16.f32 " \
        "{%0,%1,%2,%3}, {%4,%5,%6,%7}, {%8,%9}, {%0,%1,%2,%3};" \
        : "+f"((d)[0]), "+f"((d)[1]), "+f"((d)[2]), "+f"((d)[3]) \
        : "r"(a0), "r"(a1), "r"(a2), "r"(a3), "r"(b0), "r"(b1))

// ---------------------------------------------------------------------------
// prep_g (same as R13): per 64-token tile, grid (32, 8), 256 thr.
// ---------------------------------------------------------------------------
#define PTOK 64
__global__ void __launch_bounds__(256)
prep_g_kernel(const float* __restrict__ h,
              const float* __restrict__ Ww,
              const float* __restrict__ Wb,
              const float* __restrict__ aw) {
    extern __shared__ float hs[];          // [64][129]
    __shared__ float vpart[8][128];
    __shared__ float spart[4][PTOK];
    __shared__ float awsh[CDIM];
    __shared__ float vsh[CDIM];
    __shared__ float wsh[PTOK];
    __shared__ float s0sh;

    const int b  = blockIdx.y;
    const int j0 = blockIdx.x * PTOK;
    const int tid = threadIdx.x;
    const int wid = tid >> 5, lid = tid & 31;

    if (tid < CDIM) awsh[tid] = aw[CDIM + tid];
    __syncthreads();

    {
        const int dp = wid, c4 = lid * 4;
        float4 acc4 = make_float4(0.f, 0.f, 0.f, 0.f);
#pragma unroll
        for (int q = 0; q < 16; q++) {
            int d = dp + q * 8;
            float a2 = awsh[d];
            float4 wv = *(const float4*)&Ww[(size_t)d * CDIM + c4];
            acc4.x = fmaf(wv.x, a2, acc4.x);
            acc4.y = fmaf(wv.y, a2, acc4.y);
            acc4.z = fmaf(wv.z, a2, acc4.z);
            acc4.w = fmaf(wv.w, a2, acc4.w);
        }
        *(float4*)&vpart[dp][c4] = acc4;
    }

    const float* hb = h + ((size_t)b * NDIM + j0) * CDIM;
#pragma unroll
    for (int l = 0; l < 8; l++) {
        int idx = tid + l * 256;
        int r = idx >> 5, c = (idx & 31) * 4;
        float4 v = *(const float4*)&hb[(size_t)r * CDIM + c];
        float* d = &hs[r * 129 + c];
        d[0] = v.x; d[1] = v.y; d[2] = v.z; d[3] = v.w;
    }
    __syncthreads();

    if (tid < CDIM) {
        float s = 0.f;
#pragma unroll
        for (int dp = 0; dp < 8; dp++) s += vpart[dp][tid];
        vsh[tid] = s;
    } else if (wid == 7) {
        float x = 0.f;
#pragma unroll
        for (int q = 0; q < 4; q++) {
            int d = lid + 32 * q;
            x += Wb[d] * awsh[d];
        }
#pragma unroll
        for (int o = 16; o > 0; o >>= 1) x += __shfl_down_sync(0xffffffffu, x, o);
        if (lid == 0) s0sh = x;
    }
    __syncthreads();

    {
        const int part = tid >> 6, j = tid & 63;
        const int c0 = part * 32;
        float p = 0.f;
#pragma unroll
        for (int q = 0; q < 32; q++)
            p = fmaf(hs[j * 129 + c0 + q], vsh[c0 + q], p);
        spart[part][j] = p;
    }
    __syncthreads();
    if (tid < PTOK)
        wsh[tid] = expf(spart[0][tid] + spart[1][tid] + spart[2][tid] +
                        spart[3][tid] + s0sh);
    __syncthreads();

    __half* Gb = g_gT + (size_t)b * CDIM * NDIM;
#pragma unroll
    for (int l = 0; l < 32; l++) {
        int idx = tid + l * 256;
        int c = idx >> 6, j = idx & 63;
        Gb[(size_t)c * NDIM + j0 + j] = __float2half_rn(wsh[j] * hs[j * 129 + c]);
    }
    if (tid < PTOK) g_w[(size_t)b * NDIM + j0 + tid] = __float2half_rn(wsh[tid]);
}

// ---------------------------------------------------------------------------
// GEMM loaders (512 threads)
// ---------------------------------------------------------------------------
__device__ __forceinline__ void ldgA(const float* __restrict__ Ab, int it, int tid,
                                     float4 (&ra)[2]) {
    const float* src = Ab + it * BK;
#pragma unroll
    for (int l = 0; l < 2; l++) {
        int idx = tid + l * 512;           // 1024 float4 per stage
        int r = idx >> 4, c = (idx & 15) * 4;
        ra[l] = *(const float4*)&src[(size_t)r * NDIM + c];
    }
}
__device__ __forceinline__ void stsA(uint32_t sb, int s, int tid, const float4 (&ra)[2]) {
    const uint32_t base = sb + s * A_STB;
#pragma unroll
    for (int l = 0; l < 2; l++) {
        int idx = tid + l * 512;
        int r = idx >> 4, c = (idx & 15) * 4;
        __half2 h0 = __floats2half2_rn(ra[l].x, ra[l].y);
        __half2 h1 = __floats2half2_rn(ra[l].z, ra[l].w);
        asm volatile("st.shared.v2.b32 [%0], {%1,%2};"
                     :: "r"(base + (r * A_ROWP + c) * 2),
                        "r"(*(uint32_t*)&h0), "r"(*(uint32_t*)&h1) : "memory");
    }
}
__device__ __forceinline__ void cpB(uint32_t sb, int s, int it, int tid,
                                    const __half* __restrict__ Gb,
                                    const __half* __restrict__ wb) {
    const int k0 = it * BK;
    const uint32_t base = sb + B_OFFB + s * B_STB;
#pragma unroll
    for (int l = 0; l < 2; l++) {
        int idx = tid + l * 512;           // rows 0-127: 1024 chunks
        int r = idx >> 3, c = (idx & 7) * 8;
        cp16(base + (r * A_ROWP + c) * 2, Gb + (size_t)r * NDIM + k0 + c);
    }
    if (tid < 8)                            // w row (row 128): 8 chunks
        cp16(base + (128 * A_ROWP + tid * 8) * 2, wb + k0 + tid * 8);
}

// ---------------------------------------------------------------------------
// GEMM: 512 thr = 16 warps (wm 0-3 x wn 0-3), warp tile m16 x n32.
// 3-stage ring, barrier per iteration (R13 schedule). 2 CTAs/SM = 32 warps.
// ---------------------------------------------------------------------------
__global__ void __launch_bounds__(NTHR, 2)
attn_mma_kernel(const float* __restrict__ A, float* __restrict__ out) {
    extern __shared__ __align__(16) char smem[];
    const uint32_t sb = smem_u32(smem);
    const int tid = threadIdx.x;
    const int lane = tid & 31;
    const int g = lane >> 2, t = lane & 3;
    const int wid = tid >> 5;
    const int wm = wid >> 2, wn = wid & 3;
    const int b = blockIdx.y, m0 = blockIdx.x * 64;

    const float* __restrict__ Ab = A + (size_t)b * NDIM * NDIM + (size_t)m0 * NDIM;
    const __half* __restrict__ Gb = g_gT + (size_t)b * CDIM * NDIM;
    const __half* __restrict__ wb = g_w + (size_t)b * NDIM;

    float acc[4][4];                       // [ch][quad], warp tile m16 x n32
#pragma unroll
    for (int ch = 0; ch < 4; ch++)
#pragma unroll
        for (int q = 0; q < 4; q++) acc[ch][q] = 0.f;
    float dacc[4] = {0.f, 0.f, 0.f, 0.f};

    // ldmatrix lane addresses (stage-relative, bytes)
    const uint32_t aLane = ((lane & 15) * A_ROWP + (lane >> 4) * 8) * 2;
    const uint32_t bLane = aLane;

    // prologue: stages 0,1 staged; A(2) in regs
    float4 ra[2];
    ldgA(Ab, 0, tid, ra); stsA(sb, 0, tid, ra);
    cpB(sb, 0, 0, tid, Gb, wb); CP_COMMIT();
    ldgA(Ab, 1, tid, ra); stsA(sb, 1, tid, ra);
    cpB(sb, 1, 1, tid, Gb, wb); CP_COMMIT();
    ldgA(Ab, 2, tid, ra);

    int s = 0;
    for (int it = 0; it < NITER; ++it) {
        CP_WAIT1();                 // stage s resident (1 group may stay in flight)
        __syncthreads();            // stage (s+2)%3 free

        const int ns = (s + 2 >= NSTAGE) ? s + 2 - NSTAGE : s + 2;
        if (it + 2 < NITER) {
            stsA(sb, ns, tid, ra);                    // A for it+2
            cpB(sb, ns, it + 2, tid, Gb, wb);         // B for it+2
        }
        CP_COMMIT();
        if (it + 3 < NITER) ldgA(Ab, it + 3, tid, ra);

        const uint32_t aBase = sb + s * A_STB + (wm * 16 * A_ROWP) * 2 + aLane;
        const uint32_t bBase = sb + B_OFFB + s * B_STB + (wn * 32 * A_ROWP) * 2 + bLane;
        const uint32_t wRow  = sb + B_OFFB + s * B_STB + (128 * A_ROWP) * 2;
#pragma unroll
        for (int kk = 0; kk < 4; kk++) {
            const uint32_t kb = kk * 32;   // byte offset: 16 halves per kk
            uint32_t a0, a1, a2, a3;
            LDSM_X4(a0, a1, a2, a3, aBase + kb);
            uint32_t b0[4], b1[4];
#pragma unroll
            for (int nh = 0; nh < 2; nh++) {
                uint32_t r0, r1, r2, r3;
                LDSM_X4(r0, r1, r2, r3, bBase + nh * 16 * A_ROWP * 2 + kb);
                b0[nh * 2]     = r0; b1[nh * 2]     = r2;
                b0[nh * 2 + 1] = r1; b1[nh * 2 + 1] = r3;
            }
#pragma unroll
            for (int ch = 0; ch < 4; ch++)
                MMA_F16(acc[ch], a0, a1, a2, a3, b0[ch], b1[ch]);
            if (kk == wn) {        // den spread: one kk slice per wn warp
                uint32_t w0 = 0u, w1 = 0u;
                if (g == 0) {      // b0: k = kk*16 + 2t -> byte kb + 4t; b1: +16B
                    const uint32_t woff = wRow + kb + 4 * t;
                    asm volatile("ld.shared.b32 %0, [%1];" : "=r"(w0) : "r"(woff));
                    asm volatile("ld.shared.b32 %0, [%1];" : "=r"(w1) : "r"(woff + 16));
                }
                MMA_F16(dacc, a0, a1, a2, a3, w0, w1);
            }
        }
        s = (s + 1 >= NSTAGE) ? 0 : s + 1;
    }

    __syncthreads();

    // publish den partials: denS4[wn][row]; full den = sum over wn
    float* denS4 = (float*)(smem + DEN_OFFB);
    const int R = wm * 16 + g;
    if (t == 0) {
        denS4[wn * 64 + R]     = dacc[0];
        denS4[wn * 64 + R + 8] = dacc[2];
    }
    __syncthreads();

    // scale + stage to smem stg[64][132]
    float* stg = (float*)smem;
    {
        const float inv0 = 1.0f / (denS4[R] + denS4[64 + R] +
                                   denS4[128 + R] + denS4[192 + R]);
        const float inv1 = 1.0f / (denS4[R + 8] + denS4[64 + R + 8] +
                                   denS4[128 + R + 8] + denS4[192 + R + 8]);
#pragma unroll
        for (int ch = 0; ch < 4; ch++) {
            const int col = wn * 32 + ch * 8 + 2 * t;
            *(float2*)&stg[R * 132 + col] =
                make_float2(acc[ch][0] * inv0, acc[ch][1] * inv0);
            *(float2*)&stg[(R + 8) * 132 + col] =
                make_float2(acc[ch][2] * inv1, acc[ch][3] * inv1);
        }
    }
    __syncthreads();

    float* __restrict__ ob = out + ((size_t)b * NDIM + m0) * CDIM;
#pragma unroll
    for (int l = 0; l < 4; l++) {
        int idx = tid + l * 512;           // 2048 float4
        int r = idx >> 5, c = idx & 31;
        *(float4*)&ob[r * CDIM + c * 4] = *(const float4*)&stg[r * 132 + c * 4];
    }
}

// ---------------------------------------------------------------------------
extern "C" void kernel_launch(void* const* d_in, const int* in_sizes, int n_in,
                              void* d_out, int out_size) {
    (void)in_sizes; (void)n_in; (void)out_size;
    const float* h  = (const float*)d_in[0];
    const float* A  = (const float*)d_in[1];
    const float* Ww = (const float*)d_in[2];
    const float* Wb = (const float*)d_in[3];
    const float* aw = (const float*)d_in[4];
    float* out = (float*)d_out;

    cudaFuncSetAttribute(prep_g_kernel,
                         cudaFuncAttributeMaxDynamicSharedMemorySize, PTOK * 129 * 4);
    cudaFuncSetAttribute(attn_mma_kernel,
                         cudaFuncAttributeMaxDynamicSharedMemorySize, SMEM_TOTAL);

    prep_g_kernel<<<dim3(NDIM / PTOK, BDIM), 256, PTOK * 129 * 4>>>(h, Ww, Wb, aw);
    attn_mma_kernel<<<dim3(NDIM / 64, BDIM), NTHR, SMEM_TOTAL>>>(A, out);
}